// round 10
// baseline (speedup 1.0000x reference)
#include <cuda_runtime.h>
#include <cstdint>

#define B_ 256
#define T_ 2048
#define I_ 50
#define H_ 116
#define O_ 50
#define N_TOT (B_ * T_)

typedef unsigned long long u64;

// Device scratch (static allocation = allowed)
__device__ float g_xp[(size_t)N_TOT * H_];   // input projection [N, H]
__device__ float g_hs[(size_t)N_TOT * H_];   // hidden states    [N, H]

// ---------------- packed f32x2 helpers (Blackwell) ----------------
__device__ __forceinline__ u64 fma2(u64 a, u64 b, u64 c) {
    u64 d;
    asm("fma.rn.f32x2 %0, %1, %2, %3;" : "=l"(d) : "l"(a), "l"(b), "l"(c));
    return d;
}
__device__ __forceinline__ u64 add2(u64 a, u64 b) {
    u64 d;
    asm("add.rn.f32x2 %0, %1, %2;" : "=l"(d) : "l"(a), "l"(b));
    return d;
}
__device__ __forceinline__ float pair_sum(u64 a) {
    float lo = __uint_as_float((unsigned)(a & 0xFFFFFFFFull));
    float hi = __uint_as_float((unsigned)(a >> 32));
    return lo + hi;
}
__device__ __forceinline__ void cp16(void* smem, const void* gmem) {
    unsigned s = (unsigned)__cvta_generic_to_shared(smem);
    asm volatile("cp.async.ca.shared.global [%0], [%1], 16;" :: "r"(s), "l"(gmem));
}
__device__ __forceinline__ void cp8(void* smem, const void* gmem) {
    unsigned s = (unsigned)__cvta_generic_to_shared(smem);
    asm volatile("cp.async.ca.shared.global [%0], [%1], 8;" :: "r"(s), "l"(gmem));
}
#define CP_COMMIT() asm volatile("cp.async.commit_group;")
#define CP_WAIT(n)  asm volatile("cp.async.wait_group %0;" :: "n"(n))

// ================= xp GEMM: g_xp[n,j] = x[n,:]·W_ih[j,:] + b_ih[j]+b_hh[j] ==
#define XP_ROWS 32
#define XP_RPAD 52
#define XP_NT   (N_TOT / XP_ROWS)
__global__ void __launch_bounds__(256) xp_kernel(
    const float* __restrict__ x,
    const float* __restrict__ W_ih,
    const float* __restrict__ b_ih,
    const float* __restrict__ b_hh)
{
    __shared__ __align__(16) float xs[2][XP_ROWS * XP_RPAD];

    const int tid = threadIdx.x;
    const int j   = tid & 127;
    const int r2  = tid >> 7;
    const bool is_j = (j < H_);

    u64 wih[25];
    float bias = 0.f;
    if (is_j) {
        const u64* p = reinterpret_cast<const u64*>(W_ih + j * I_);
        #pragma unroll
        for (int q = 0; q < 25; q++) wih[q] = p[q];
        bias = b_ih[j] + b_hh[j];
    }

    auto stage = [&](int tile, int buf) {
        const float* src = x + (size_t)tile * (XP_ROWS * I_);
        for (int i = tid; i < XP_ROWS * 25; i += 256) {
            int row = i / 25, c = i - 25 * row;
            cp8(&xs[buf][row * XP_RPAD + 2 * c], src + row * I_ + 2 * c);
        }
    };

    int tile = blockIdx.x;
    if (tile < XP_NT) stage(tile, 0);
    CP_COMMIT();

    int pb = 0;
    for (; tile < XP_NT; tile += gridDim.x) {
        const int nxt = tile + gridDim.x;
        if (nxt < XP_NT) stage(nxt, pb ^ 1);
        CP_COMMIT();
        CP_WAIT(1);
        __syncthreads();

        if (is_j) {
            float* orow = g_xp + (size_t)tile * XP_ROWS * H_ + j;
            #pragma unroll 2
            for (int i = 0; i < XP_ROWS / 2; i++) {
                const int row = 2 * i + r2;
                const float* rbase = xs[pb] + row * XP_RPAD;
                const ulonglong2* av =
                    reinterpret_cast<const ulonglong2*>(rbase);
                u64 a0 = 0, a1 = 0, a2 = 0, a3 = 0;
                #pragma unroll
                for (int q = 0; q < 12; q++) {
                    ulonglong2 v = av[q];
                    if (q & 1) {
                        a2 = fma2(wih[2 * q],     v.x, a2);
                        a3 = fma2(wih[2 * q + 1], v.y, a3);
                    } else {
                        a0 = fma2(wih[2 * q],     v.x, a0);
                        a1 = fma2(wih[2 * q + 1], v.y, a1);
                    }
                }
                a0 = fma2(wih[24],
                          reinterpret_cast<const u64*>(rbase)[24], a0);
                orow[(size_t)row * H_] =
                    pair_sum(add2(add2(a0, a1), add2(a2, a3))) + bias;
            }
        }
        __syncthreads();
        pb ^= 1;
    }
}

// ================= FC GEMM: out[n,o] = hs[n,:]·W_fc[o,:] + b_fc[o] =========
// k-split lane pairs: lanes (2o, 2o+1) hold half of W_fc row o in regs,
// partials merged via shfl.bfly(1). 2 CTAs/SM.
#define FC_ROWS 16
#define FC_NT   (N_TOT / FC_ROWS)
__global__ void __launch_bounds__(256, 2) fc_kernel(
    const float* __restrict__ W_fc,
    const float* __restrict__ b_fc,
    float* __restrict__ out)
{
    __shared__ __align__(16) float hs_s[2][FC_ROWS * H_ + 4];

    const int tid  = threadIdx.x;
    const int o2   = tid & 127;
    const int o    = o2 >> 1;
    const int half = o2 & 1;
    const int g    = tid >> 7;
    const bool is_o = (o < O_);

    u64 w[30];
    #pragma unroll
    for (int q = 0; q < 30; q++) w[q] = 0ull;
    float bias = 0.f;
    if (is_o) {
        const u64* ws =
            reinterpret_cast<const u64*>(W_fc + o * H_ + 60 * half);
        const int nw = 30 - 2 * half;
        #pragma unroll
        for (int q = 0; q < 30; q++) if (q < nw) w[q] = ws[q];
        bias = b_fc[o];
    }

    const float* hs = g_hs;
    int tile = blockIdx.x;
    if (tile < FC_NT) {
        const float* src = hs + (size_t)tile * (FC_ROWS * H_);
        for (int i = tid; i < (FC_ROWS * H_) / 4; i += 256)
            cp16(&hs_s[0][4 * i], src + 4 * i);
    }
    CP_COMMIT();

    int pb = 0;
    for (; tile < FC_NT; tile += gridDim.x) {
        const int nxt = tile + gridDim.x;
        if (nxt < FC_NT) {
            const float* src = hs + (size_t)nxt * (FC_ROWS * H_);
            for (int i = tid; i < (FC_ROWS * H_) / 4; i += 256)
                cp16(&hs_s[pb ^ 1][4 * i], src + 4 * i);
        }
        CP_COMMIT();
        CP_WAIT(1);
        __syncthreads();

        #pragma unroll
        for (int i = 0; i < FC_ROWS / 2; i++) {
            const int row = 2 * i + g;
            const ulonglong2* hv = reinterpret_cast<const ulonglong2*>(
                hs_s[pb] + row * H_ + 60 * half);
            u64 a0 = 0, a1 = 0, a2 = 0, a3 = 0;
            #pragma unroll
            for (int q = 0; q < 15; q++) {
                ulonglong2 v = hv[q];
                if (q & 1) {
                    a2 = fma2(w[2 * q],     v.x, a2);
                    a3 = fma2(w[2 * q + 1], v.y, a3);
                } else {
                    a0 = fma2(w[2 * q],     v.x, a0);
                    a1 = fma2(w[2 * q + 1], v.y, a1);
                }
            }
            float part = pair_sum(add2(add2(a0, a1), add2(a2, a3)));
            float oth  = __shfl_xor_sync(0xFFFFFFFFu, part, 1);
            if (is_o && half == 0)
                out[(size_t)(tile * FC_ROWS + row) * O_ + o] =
                    part + oth + bias;
        }
        __syncthreads();
        pb ^= 1;
    }
}

// ================= recurrence: h(t+1) = relu(xp(t) + W_hh·h(t)) ============
// 128 CTAs x 128 threads; CTA c handles batch rows 2c, 2c+1. Thread j keeps
// one W_hh row in registers and computes h[j] for BOTH rows each step:
// barrier / LDS-latency / reduce tail amortized over 2 rows, and the two
// rows' FMA chains interleave for free ILP. xp prefetched 4 steps ahead via
// __ldg into 4 rotating register pairs (unroll-4 loop).
// h_s tail [116,128) stays zero; lanes j>=116 compute harmless garbage into
// the tail (never read: hv covers exactly [0,116)) and skip the STG.
__global__ void __launch_bounds__(128, 2) rnn_kernel(
    const float* __restrict__ W_hh)
{
    __shared__ __align__(16) float h_s[2][2][128];   // [pingpong][row][j]

    const int j = threadIdx.x;
    const bool comp = (j < H_);
    const int jc = comp ? j : (H_ - 1);              // clamped for safe loads
    const size_t b0 = blockIdx.x * 2;
    const size_t b1 = b0 + 1;

    h_s[0][0][j] = 0.f; h_s[0][1][j] = 0.f;
    h_s[1][0][j] = 0.f; h_s[1][1][j] = 0.f;

    u64 w[58];
    {
        const u64* ws = reinterpret_cast<const u64*>(W_hh + jc * H_);
        #pragma unroll
        for (int q = 0; q < 58; q++) w[q] = ws[q];
    }

    const float* xp0 = g_xp + b0 * T_ * H_ + jc;
    const float* xp1 = g_xp + b1 * T_ * H_ + jc;
    float xA0, xA1, xB0, xB1, xC0, xC1, xD0, xD1;
    xA0 = __ldg(xp0);            xA1 = __ldg(xp1);
    xB0 = __ldg(xp0 + H_);       xB1 = __ldg(xp1 + H_);
    xC0 = __ldg(xp0 + 2 * H_);   xC1 = __ldg(xp1 + 2 * H_);
    xD0 = __ldg(xp0 + 3 * H_);   xD1 = __ldg(xp1 + 3 * H_);
    __syncthreads();

    float* h0p = g_hs + b0 * T_ * H_ + j;
    float* h1p = g_hs + b1 * T_ * H_ + j;
    int p = 0;

#define RNN_STEP(X0, X1, TN)                                                 \
    {                                                                        \
        u64 a0 = (u64)__float_as_uint(X0);                                   \
        u64 c0 = (u64)__float_as_uint(X1);                                   \
        if (comp && (TN) < T_) {                                             \
            X0 = __ldg(xp0 + (size_t)(TN) * H_);                             \
            X1 = __ldg(xp1 + (size_t)(TN) * H_);                             \
        }                                                                    \
        u64 a1 = 0, a2 = 0, a3 = 0, c1 = 0, c2 = 0, c3 = 0;                  \
        const ulonglong2* h0v =                                              \
            reinterpret_cast<const ulonglong2*>(h_s[p][0]);                  \
        const ulonglong2* h1v =                                              \
            reinterpret_cast<const ulonglong2*>(h_s[p][1]);                  \
        _Pragma("unroll")                                                    \
        for (int q = 0; q < 29; q++) {                                       \
            ulonglong2 v0 = h0v[q];                                          \
            ulonglong2 v1 = h1v[q];                                          \
            if (q & 1) {                                                     \
                a2 = fma2(w[2 * q],     v0.x, a2);                           \
                a3 = fma2(w[2 * q + 1], v0.y, a3);                           \
                c2 = fma2(w[2 * q],     v1.x, c2);                           \
                c3 = fma2(w[2 * q + 1], v1.y, c3);                           \
            } else {                                                         \
                a0 = fma2(w[2 * q],     v0.x, a0);                           \
                a1 = fma2(w[2 * q + 1], v0.y, a1);                           \
                c0 = fma2(w[2 * q],     v1.x, c0);                           \
                c1 = fma2(w[2 * q + 1], v1.y, c1);                           \
            }                                                                \
        }                                                                    \
        float h0 = fmaxf(pair_sum(add2(add2(a0, a1), add2(a2, a3))), 0.f);   \
        float h1 = fmaxf(pair_sum(add2(add2(c0, c1), add2(c2, c3))), 0.f);   \
        h_s[p ^ 1][0][j] = h0;                                               \
        h_s[p ^ 1][1][j] = h1;                                               \
        if (comp) {                                                          \
            h0p[0] = h0; h0p += H_;                                          \
            h1p[0] = h1; h1p += H_;                                          \
        }                                                                    \
        __syncthreads();                                                     \
        p ^= 1;                                                              \
    }

    for (int t = 0; t < T_; t += 4) {
        RNN_STEP(xA0, xA1, t + 4)
        RNN_STEP(xB0, xB1, t + 5)
        RNN_STEP(xC0, xC1, t + 6)
        RNN_STEP(xD0, xD1, t + 7)
    }
#undef RNN_STEP
}

// Probe kernels: occupy ncu capture slots so slot 4 = rnn_kernel.
__global__ void probe_kernel() {
    if (threadIdx.x == 0 && blockIdx.x == 0) g_xp[0] = g_xp[0];
}

// ---------------- launch ----------------
extern "C" void kernel_launch(void* const* d_in, const int* in_sizes, int n_in,
                              void* d_out, int out_size)
{
    const float* x    = (const float*)d_in[0];
    const float* W_ih = (const float*)d_in[1];
    const float* b_ih = (const float*)d_in[2];
    const float* W_hh = (const float*)d_in[3];
    const float* b_hh = (const float*)d_in[4];
    const float* W_fc = (const float*)d_in[5];
    const float* b_fc = (const float*)d_in[6];
    float* out = (float*)d_out;

    xp_kernel<<<4096, 256>>>(x, W_ih, b_ih, b_hh);
    probe_kernel<<<1, 32>>>();
    probe_kernel<<<1, 32>>>();
    rnn_kernel<<<B_ / 2, 128>>>(W_hh);
    fc_kernel<<<2048, 256>>>(W_fc, b_fc, out);
}

// round 11
// speedup vs baseline: 1.0837x; 1.0837x over previous
#include <cuda_runtime.h>
#include <cstdint>

#define B_ 256
#define T_ 2048
#define I_ 50
#define H_ 116
#define O_ 50
#define N_TOT (B_ * T_)

typedef unsigned long long u64;

// Device scratch (static allocation = allowed)
__device__ float g_xp[(size_t)N_TOT * H_];   // input projection [N, H]
__device__ float g_hs[(size_t)N_TOT * H_];   // hidden states    [N, H]

// ---------------- packed f32x2 helpers (Blackwell) ----------------
__device__ __forceinline__ u64 fma2(u64 a, u64 b, u64 c) {
    u64 d;
    asm("fma.rn.f32x2 %0, %1, %2, %3;" : "=l"(d) : "l"(a), "l"(b), "l"(c));
    return d;
}
__device__ __forceinline__ u64 add2(u64 a, u64 b) {
    u64 d;
    asm("add.rn.f32x2 %0, %1, %2;" : "=l"(d) : "l"(a), "l"(b));
    return d;
}
__device__ __forceinline__ float pair_sum(u64 a) {
    float lo = __uint_as_float((unsigned)(a & 0xFFFFFFFFull));
    float hi = __uint_as_float((unsigned)(a >> 32));
    return lo + hi;
}
__device__ __forceinline__ void cp16(void* smem, const void* gmem) {
    unsigned s = (unsigned)__cvta_generic_to_shared(smem);
    asm volatile("cp.async.ca.shared.global [%0], [%1], 16;" :: "r"(s), "l"(gmem));
}
__device__ __forceinline__ void cp8(void* smem, const void* gmem) {
    unsigned s = (unsigned)__cvta_generic_to_shared(smem);
    asm volatile("cp.async.ca.shared.global [%0], [%1], 8;" :: "r"(s), "l"(gmem));
}
#define CP_COMMIT() asm volatile("cp.async.commit_group;")
#define CP_WAIT(n)  asm volatile("cp.async.wait_group %0;" :: "n"(n))

// ================= xp GEMM: g_xp[n,j] = x[n,:]·W_ih[j,:] + b_ih[j]+b_hh[j] ==
#define XP_ROWS 32
#define XP_RPAD 52
#define XP_NT   (N_TOT / XP_ROWS)
__global__ void __launch_bounds__(256) xp_kernel(
    const float* __restrict__ x,
    const float* __restrict__ W_ih,
    const float* __restrict__ b_ih,
    const float* __restrict__ b_hh)
{
    __shared__ __align__(16) float xs[2][XP_ROWS * XP_RPAD];

    const int tid = threadIdx.x;
    const int j   = tid & 127;
    const int r2  = tid >> 7;
    const bool is_j = (j < H_);

    u64 wih[25];
    float bias = 0.f;
    if (is_j) {
        const u64* p = reinterpret_cast<const u64*>(W_ih + j * I_);
        #pragma unroll
        for (int q = 0; q < 25; q++) wih[q] = p[q];
        bias = b_ih[j] + b_hh[j];
    }

    auto stage = [&](int tile, int buf) {
        const float* src = x + (size_t)tile * (XP_ROWS * I_);
        for (int i = tid; i < XP_ROWS * 25; i += 256) {
            int row = i / 25, c = i - 25 * row;
            cp8(&xs[buf][row * XP_RPAD + 2 * c], src + row * I_ + 2 * c);
        }
    };

    int tile = blockIdx.x;
    if (tile < XP_NT) stage(tile, 0);
    CP_COMMIT();

    int pb = 0;
    for (; tile < XP_NT; tile += gridDim.x) {
        const int nxt = tile + gridDim.x;
        if (nxt < XP_NT) stage(nxt, pb ^ 1);
        CP_COMMIT();
        CP_WAIT(1);
        __syncthreads();

        if (is_j) {
            float* orow = g_xp + (size_t)tile * XP_ROWS * H_ + j;
            #pragma unroll 2
            for (int i = 0; i < XP_ROWS / 2; i++) {
                const int row = 2 * i + r2;
                const float* rbase = xs[pb] + row * XP_RPAD;
                const ulonglong2* av =
                    reinterpret_cast<const ulonglong2*>(rbase);
                u64 a0 = 0, a1 = 0, a2 = 0, a3 = 0;
                #pragma unroll
                for (int q = 0; q < 12; q++) {
                    ulonglong2 v = av[q];
                    if (q & 1) {
                        a2 = fma2(wih[2 * q],     v.x, a2);
                        a3 = fma2(wih[2 * q + 1], v.y, a3);
                    } else {
                        a0 = fma2(wih[2 * q],     v.x, a0);
                        a1 = fma2(wih[2 * q + 1], v.y, a1);
                    }
                }
                a0 = fma2(wih[24],
                          reinterpret_cast<const u64*>(rbase)[24], a0);
                orow[(size_t)row * H_] =
                    pair_sum(add2(add2(a0, a1), add2(a2, a3))) + bias;
            }
        }
        __syncthreads();
        pb ^= 1;
    }
}

// ================= FC GEMM: out[n,o] = hs[n,:]·W_fc[o,:] + b_fc[o] =========
// k-split lane pairs: lanes (2o, 2o+1) hold half of W_fc row o in regs,
// partials merged via shfl.bfly(1). 2 CTAs/SM.
#define FC_ROWS 16
#define FC_NT   (N_TOT / FC_ROWS)
__global__ void __launch_bounds__(256, 2) fc_kernel(
    const float* __restrict__ W_fc,
    const float* __restrict__ b_fc,
    float* __restrict__ out)
{
    __shared__ __align__(16) float hs_s[2][FC_ROWS * H_ + 4];

    const int tid  = threadIdx.x;
    const int o2   = tid & 127;
    const int o    = o2 >> 1;
    const int half = o2 & 1;
    const int g    = tid >> 7;
    const bool is_o = (o < O_);

    u64 w[30];
    #pragma unroll
    for (int q = 0; q < 30; q++) w[q] = 0ull;
    float bias = 0.f;
    if (is_o) {
        const u64* ws =
            reinterpret_cast<const u64*>(W_fc + o * H_ + 60 * half);
        const int nw = 30 - 2 * half;
        #pragma unroll
        for (int q = 0; q < 30; q++) if (q < nw) w[q] = ws[q];
        bias = b_fc[o];
    }

    const float* hs = g_hs;
    int tile = blockIdx.x;
    if (tile < FC_NT) {
        const float* src = hs + (size_t)tile * (FC_ROWS * H_);
        for (int i = tid; i < (FC_ROWS * H_) / 4; i += 256)
            cp16(&hs_s[0][4 * i], src + 4 * i);
    }
    CP_COMMIT();

    int pb = 0;
    for (; tile < FC_NT; tile += gridDim.x) {
        const int nxt = tile + gridDim.x;
        if (nxt < FC_NT) {
            const float* src = hs + (size_t)nxt * (FC_ROWS * H_);
            for (int i = tid; i < (FC_ROWS * H_) / 4; i += 256)
                cp16(&hs_s[pb ^ 1][4 * i], src + 4 * i);
        }
        CP_COMMIT();
        CP_WAIT(1);
        __syncthreads();

        #pragma unroll
        for (int i = 0; i < FC_ROWS / 2; i++) {
            const int row = 2 * i + g;
            const ulonglong2* hv = reinterpret_cast<const ulonglong2*>(
                hs_s[pb] + row * H_ + 60 * half);
            u64 a0 = 0, a1 = 0, a2 = 0, a3 = 0;
            #pragma unroll
            for (int q = 0; q < 15; q++) {
                ulonglong2 v = hv[q];
                if (q & 1) {
                    a2 = fma2(w[2 * q],     v.x, a2);
                    a3 = fma2(w[2 * q + 1], v.y, a3);
                } else {
                    a0 = fma2(w[2 * q],     v.x, a0);
                    a1 = fma2(w[2 * q + 1], v.y, a1);
                }
            }
            float part = pair_sum(add2(add2(a0, a1), add2(a2, a3)));
            float oth  = __shfl_xor_sync(0xFFFFFFFFu, part, 1);
            if (is_o && half == 0)
                out[(size_t)(tile * FC_ROWS + row) * O_ + o] =
                    part + oth + bias;
        }
        __syncthreads();
        pb ^= 1;
    }
}

// ================= recurrence: h(t+1) = relu(xp(t) + W_hh·h(t)) ============
// 256 CTAs x 256 threads; ONE batch row per CTA, 2 CTAs/SM (low regs).
// Lane pair (2j, 2j+1) computes h[j]: half0 holds W_hh[j][0:60) (30 u64),
// half1 holds W_hh[j][60:116) (28 u64 + 2 zeros). Only ~58 weight regs per
// thread -> ptxas has room to hoist all 15 h-loads (LDS.128, 2-address
// broadcast) to the top of each step, exposing LDS latency ONCE per step
// instead of 29x. Partials merged via shfl.bfly(1); even lane does
// relu + STS + STG. xp prefetched 4 steps ahead via __ldg (even lanes).
// h_s tail [116,120) stays zero (matches half1's zero weights).
__global__ void __launch_bounds__(256, 2) rnn_kernel(
    const float* __restrict__ W_hh)
{
    __shared__ __align__(16) float h_s[2][128];   // ping-pong, 116 used

    const int s    = threadIdx.x;
    const int j    = s >> 1;
    const int half = s & 1;
    const int b    = blockIdx.x;
    const bool comp = (s < 232);                  // j < 116
    const bool ldx  = comp && (half == 0);

    h_s[0][s & 127] = 0.f;
    h_s[1][s & 127] = 0.f;

    u64 w[30];
    #pragma unroll
    for (int q = 0; q < 30; q++) w[q] = 0ull;
    if (comp) {
        const u64* ws =
            reinterpret_cast<const u64*>(W_hh + j * H_ + 60 * half);
        const int nw = 30 - 2 * half;
        #pragma unroll
        for (int q = 0; q < 30; q++) if (q < nw) w[q] = ws[q];
    }

    const float* xpj = g_xp + (size_t)b * T_ * H_ + j;
    float xA = 0.f, xB = 0.f, xC = 0.f, xD = 0.f;
    if (ldx) {
        xA = __ldg(xpj);
        xB = __ldg(xpj + H_);
        xC = __ldg(xpj + 2 * H_);
        xD = __ldg(xpj + 3 * H_);
    }
    __syncthreads();

    float* hsp = g_hs + (size_t)b * T_ * H_ + j;
    int p = 0;

#define RNN_STEP(XR, TN)                                                     \
    {                                                                        \
        u64 a0 = (u64)__float_as_uint(XR);       /* 0 for half1 */           \
        if (ldx && (TN) < T_) XR = __ldg(xpj + (size_t)(TN) * H_);           \
        u64 a1 = 0, a2 = 0, a3 = 0;                                          \
        const ulonglong2* hv =                                               \
            reinterpret_cast<const ulonglong2*>(h_s[p]) + 15 * half;         \
        _Pragma("unroll")                                                    \
        for (int q = 0; q < 15; q++) {                                       \
            ulonglong2 v = hv[q];                                            \
            if (q & 1) { a2 = fma2(w[2 * q],     v.x, a2);                   \
                         a3 = fma2(w[2 * q + 1], v.y, a3); }                 \
            else       { a0 = fma2(w[2 * q],     v.x, a0);                   \
                         a1 = fma2(w[2 * q + 1], v.y, a1); }                 \
        }                                                                    \
        float part = pair_sum(add2(add2(a0, a1), add2(a2, a3)));             \
        float oth  = __shfl_xor_sync(0xFFFFFFFFu, part, 1);                  \
        if (ldx) {                                                           \
            float h = fmaxf(part + oth, 0.f);                                \
            h_s[p ^ 1][j] = h;                                               \
            hsp[0] = h; hsp += H_;                                           \
        }                                                                    \
        __syncthreads();                                                     \
        p ^= 1;                                                              \
    }

    for (int t = 0; t < T_; t += 4) {
        RNN_STEP(xA, t + 4)
        RNN_STEP(xB, t + 5)
        RNN_STEP(xC, t + 6)
        RNN_STEP(xD, t + 7)
    }
#undef RNN_STEP
}

// Probe kernels: occupy ncu capture slots so slot 4 = rnn_kernel.
__global__ void probe_kernel() {
    if (threadIdx.x == 0 && blockIdx.x == 0) g_xp[0] = g_xp[0];
}

// ---------------- launch ----------------
extern "C" void kernel_launch(void* const* d_in, const int* in_sizes, int n_in,
                              void* d_out, int out_size)
{
    const float* x    = (const float*)d_in[0];
    const float* W_ih = (const float*)d_in[1];
    const float* b_ih = (const float*)d_in[2];
    const float* W_hh = (const float*)d_in[3];
    const float* b_hh = (const float*)d_in[4];
    const float* W_fc = (const float*)d_in[5];
    const float* b_fc = (const float*)d_in[6];
    float* out = (float*)d_out;

    xp_kernel<<<4096, 256>>>(x, W_ih, b_ih, b_hh);
    probe_kernel<<<1, 32>>>();
    probe_kernel<<<1, 32>>>();
    rnn_kernel<<<B_, 256>>>(W_hh);
    fc_kernel<<<2048, 256>>>(W_fc, b_fc, out);
}